// round 15
// baseline (speedup 1.0000x reference)
#include <cuda_runtime.h>
#include <cuda_fp16.h>
#include <cstdint>

// Problem constants (fixed by the dataset)
#define NXc   1024          // input features (K)
#define NFc   4096          // output features (N)
#define BITSc 8             // bit planes
#define Gc    128           // NX/8 packed groups
#define Mc    4096          // tokens (2*2048)

#define BM 128
#define BN 128
#define KC 16               // k-chunks of 64
#define NSTEP (KC * 4)      // 64 flat (chunk, ks) steps

// Fragment-major fp16 tiles (uint32 = half2), 16KB each:
//   A tile: [mt(8)][ks(4)][lane(32)][4 u32]
//   B tile: [ntp(8)][ks(4)][lane(32)][4 u32]  (pair-interleaved: two n8 frags)
#define TILE_U32   4096

__device__ uint32_t g_Xt[(size_t)Mc * NXc / 2];   // [m_blk(32)][kc(16)][TILE]
__device__ uint32_t g_Wt[(size_t)NFc * NXc / 2];  // [n_blk(32)][kc(16)][TILE]

// ---------------------------------------------------------------------------
__device__ __forceinline__ uint32_t pack_h2(float lo, float hi) {
    __half2 h = __floats2half2_rn(lo, hi);   // lo -> low 16 bits
    return *reinterpret_cast<uint32_t*>(&h);
}
__device__ __forceinline__ void mma_f16(float* d, const uint32_t* a, const uint32_t* b) {
    asm volatile(
        "mma.sync.aligned.m16n8k16.row.col.f32.f16.f16.f32 "
        "{%0,%1,%2,%3}, {%4,%5,%6,%7}, {%8,%9}, {%0,%1,%2,%3};"
        : "+f"(d[0]), "+f"(d[1]), "+f"(d[2]), "+f"(d[3])
        : "r"(a[0]), "r"(a[1]), "r"(a[2]), "r"(a[3]), "r"(b[0]), "r"(b[1]));
}
// exact sign-inject: s if bit (7-j) of the ORIGINAL byte is 1, else -s.
// nb is the pre-complemented byte (set bit => positive after XOR trick).
__device__ __forceinline__ float sgn_inj(float s, uint32_t nb, int j) {
    uint32_t u = __float_as_uint(s) ^ ((nb << (24 + j)) & 0x80000000u);
    return __uint_as_float(u);
}

// ---------------------------------------------------------------------------
// Fused prep kernel:
//   blocks [0,512):    decode W (4 groups / thread, int4 binary loads),
//                      pair-interleaved layout (verified R7/R8/R12/R14)
//   blocks [512,2560): repack x (R4/R11 layout, verified)
// ---------------------------------------------------------------------------
__global__ void __launch_bounds__(256)
prep_kernel(const int* __restrict__ binary, const float* __restrict__ scale,
            const float* __restrict__ x) {
    if (blockIdx.x < 512) {
        // ---- decode: packed signs -> W, pair-interleaved fp16 B layout ----
        int tid = blockIdx.x * 256 + threadIdx.x;   // NF * G/4 threads
        int f = tid >> 5;          // output feature
        int q = tid & 31;          // quad-group index: groups 4q..4q+3

        float w[32];               // [e(4 groups)][j(8)]
#pragma unroll
        for (int j = 0; j < 32; j++) w[j] = 0.0f;

#pragma unroll
        for (int k = 0; k < BITSc; k++) {
            int4 bb = *reinterpret_cast<const int4*>(
                binary + (size_t)(k * NFc + f) * Gc + 4 * q);
            float s = __ldg(scale + k * NFc + f);
            uint32_t n0 = ~(uint32_t)bb.x;
            uint32_t n1 = ~(uint32_t)bb.y;
            uint32_t n2 = ~(uint32_t)bb.z;
            uint32_t n3 = ~(uint32_t)bb.w;
#pragma unroll
            for (int j = 0; j < 8; j++) {
                w[j]      += sgn_inj(s, n0, j);
                w[8 + j]  += sgn_inj(s, n1, j);
                w[16 + j] += sgn_inj(s, n2, j);
                w[24 + j] += sgn_inj(s, n3, j);
            }
        }

        int n_blk = f >> 7;
        int nt    = (f & 127) >> 3;    // 0..15
        int ntp   = nt >> 1;           // pair index 0..7
        int half  = nt & 1;            // low/high half of the uint4
        int col   = f & 7;
        int kc    = q >> 1;            // k-chunk (BK=64)

        uint32_t* tile = g_Wt + (size_t)(n_blk * KC + kc) * TILE_U32;
        // two old sub-threads: t=0 covers groups (4q,4q+1), t=1 (4q+2,4q+3)
#pragma unroll
        for (int t = 0; t < 2; t++) {
            int ks = (q & 1) * 2 + t;      // k16-step within chunk
            const float* wt = w + 16 * t;
#pragma unroll
            for (int c = 0; c < 4; c++) {
                uint2 v;
                v.x = pack_h2(wt[2 * c], wt[2 * c + 1]);          // reg b0
                v.y = pack_h2(wt[8 + 2 * c], wt[9 + 2 * c]);      // reg b1
                *reinterpret_cast<uint2*>(
                    tile + ((ntp * 4 + ks) * 32 + col * 4 + c) * 4 + half * 2) = v;
            }
        }
    } else {
        // ---- repack: x -> fragment-major fp16 A layout ----
        int tid  = (blockIdx.x - 512) * 256 + threadIdx.x;  // M*K/8 threads
        int lane = tid & 31;
        int ks   = (tid >> 5) & 3;
        int mt   = (tid >> 7) & 7;
        int kc   = (tid >> 10) & (KC - 1);
        int mblk = tid >> 14;

        int row = mblk * BM + mt * 16 + (lane >> 2);
        int k0  = kc * 64 + ks * 16 + (lane & 3) * 2;

        const float* r0 = x + (size_t)row * NXc;
        const float* r1 = r0 + 8 * NXc;

        float2 p00 = *reinterpret_cast<const float2*>(r0 + k0);
        float2 p10 = *reinterpret_cast<const float2*>(r1 + k0);
        float2 p01 = *reinterpret_cast<const float2*>(r0 + k0 + 8);
        float2 p11 = *reinterpret_cast<const float2*>(r1 + k0 + 8);

        uint4 v;
        v.x = pack_h2(p00.x, p00.y);
        v.y = pack_h2(p10.x, p10.y);
        v.z = pack_h2(p01.x, p01.y);
        v.w = pack_h2(p11.x, p11.y);

        uint32_t* tile = g_Xt + (size_t)(mblk * KC + kc) * TILE_U32;
        *reinterpret_cast<uint4*>(tile + ((mt * 4 + ks) * 32 + lane) * 4) = v;
    }
}

// ---------------------------------------------------------------------------
// GEMM: barrier-free, smem-free fp16 mma.sync (R11/R14 trunk — FROZEN).
// 128x128 CTA tile, 256 threads (8 warps, 2m x 4n, warp tile 64x32).
// Operands stream via LDG from fragment-major global layouts into
// double-buffered register fragments. B pair-interleaved: 2x LDG.128/step.
// ---------------------------------------------------------------------------
__global__ void __launch_bounds__(256, 2)
gemm_kernel(const float* __restrict__ bias, float* __restrict__ out) {
    const int tid  = threadIdx.x;
    const int lane = tid & 31;
    const int wid  = tid >> 5;
    const int wm   = wid >> 2;      // 0..1
    const int wn   = wid & 3;       // 0..3
    const int n_blk = blockIdx.x;
    const int m_blk = blockIdx.y;

    // warp-private fragment stream bases (u32 units)
    // A frag (i, step s):   Aw + (s>>2)*4096 + (s&3)*128 + i*512   (uint4)
    // B pair (jp, step s):  Bw + (s>>2)*4096 + (s&3)*128 + jp*512  (uint4)
    const uint32_t* Aw = g_Xt + (size_t)m_blk * KC * TILE_U32
                       + ((wm * 4) * 4 * 32 + lane) * 4;
    const uint32_t* Bw = g_Wt + (size_t)n_blk * KC * TILE_U32
                       + (((wn * 2) * 4) * 32 + lane) * 4;

    float acc[4][4][4];
#pragma unroll
    for (int i = 0; i < 4; i++)
#pragma unroll
        for (int j = 0; j < 4; j++)
#pragma unroll
            for (int r = 0; r < 4; r++) acc[i][j][r] = 0.0f;

    uint32_t a[2][4][4], b[2][4][2];

    // preload step 0
#pragma unroll
    for (int i = 0; i < 4; i++) {
        uint4 v = __ldg(reinterpret_cast<const uint4*>(Aw + i * 512));
        a[0][i][0] = v.x; a[0][i][1] = v.y; a[0][i][2] = v.z; a[0][i][3] = v.w;
    }
#pragma unroll
    for (int jp = 0; jp < 2; jp++) {
        uint4 v = __ldg(reinterpret_cast<const uint4*>(Bw + jp * 512));
        b[0][2 * jp][0]     = v.x; b[0][2 * jp][1]     = v.y;
        b[0][2 * jp + 1][0] = v.z; b[0][2 * jp + 1][1] = v.w;
    }

#pragma unroll 4
    for (int s = 0; s < NSTEP; s++) {
        const int cur = s & 1, nxt = cur ^ 1;

        // prefetch step s+1 (overlaps this step's 16 MMAs)
        if (s < NSTEP - 1) {
            const int sn  = s + 1;
            const int off = (sn >> 2) * 4096 + (sn & 3) * 128;
#pragma unroll
            for (int i = 0; i < 4; i++) {
                uint4 v = __ldg(reinterpret_cast<const uint4*>(Aw + off + i * 512));
                a[nxt][i][0] = v.x; a[nxt][i][1] = v.y;
                a[nxt][i][2] = v.z; a[nxt][i][3] = v.w;
            }
#pragma unroll
            for (int jp = 0; jp < 2; jp++) {
                uint4 v = __ldg(reinterpret_cast<const uint4*>(Bw + off + jp * 512));
                b[nxt][2 * jp][0]     = v.x; b[nxt][2 * jp][1]     = v.y;
                b[nxt][2 * jp + 1][0] = v.z; b[nxt][2 * jp + 1][1] = v.w;
            }
        }

#pragma unroll
        for (int i = 0; i < 4; i++)
#pragma unroll
            for (int j = 0; j < 4; j++)
                mma_f16(acc[i][j], a[cur][i], b[cur][j]);
    }

    // epilogue: c0,c1 at (row, col/col+1); c2,c3 at (row+8, ·)
    const int row0 = m_blk * BM + wm * 64 + (lane >> 2);
    const int col0 = n_blk * BN + wn * 32 + (lane & 3) * 2;
#pragma unroll
    for (int j = 0; j < 4; j++) {
        const int n = col0 + j * 8;
        const float2 bv = *reinterpret_cast<const float2*>(bias + n);
#pragma unroll
        for (int i = 0; i < 4; i++) {
            const int m = row0 + i * 16;
            float2 v0, v1;
            v0.x = acc[i][j][0] + bv.x;
            v0.y = acc[i][j][1] + bv.y;
            v1.x = acc[i][j][2] + bv.x;
            v1.y = acc[i][j][3] + bv.y;
            *reinterpret_cast<float2*>(out + (size_t)m * NFc + n)       = v0;
            *reinterpret_cast<float2*>(out + (size_t)(m + 8) * NFc + n) = v1;
        }
    }
}

// ---------------------------------------------------------------------------
// Launch
// ---------------------------------------------------------------------------
extern "C" void kernel_launch(void* const* d_in, const int* in_sizes, int n_in,
                              void* d_out, int out_size) {
    const float* x      = (const float*)d_in[0];
    const int*   binary = (const int*)  d_in[1];
    const float* scale  = (const float*)d_in[2];
    const float* bias   = (const float*)d_in[3];
    float*       out    = (float*)d_out;

    prep_kernel<<<2560, 256>>>(binary, scale, x);

    dim3 grid(NFc / BN, Mc / BM);      // 32 x 32
    gemm_kernel<<<grid, 256>>>(bias, out);
}